// round 14
// baseline (speedup 1.0000x reference)
#include <cuda_runtime.h>
#include <cuda_fp16.h>
#include <cstdint>

// ---------------- problem constants ----------------
#define KDIM   768
#define HDIM   1024
#define BMAX   65536
#define GT     256          // 8 warps: 2 Mp x 4 Np
#define NCHUNK (KDIM / 64)  // 12 K-chunks of 64

// ---------------- scratch (device globals; no allocation APIs) ----------------
__device__ __align__(256) __half g_Ah[(size_t)2 * BMAX * KDIM];  // [white;black] fp16
__device__ __align__(256) __half g_Bh[(size_t)HDIM * KDIM];      // ft_w fp16
__device__ __align__(256) float  g_l1part[(size_t)8 * BMAX * 8]; // [slot][row][8]

// ---------------- PTX helpers (plain sm_103-safe: cp.async / ldmatrix / mma.sync) ----
__device__ __forceinline__ uint32_t smem_u32(const void* p) {
    uint32_t a;
    asm("{ .reg .u64 t; cvta.to.shared.u64 t, %1; cvt.u32.u64 %0, t; }" : "=r"(a) : "l"(p));
    return a;
}

__device__ __forceinline__ void cpa16(uint32_t s, const void* g) {
    asm volatile("cp.async.cg.shared.global [%0], [%1], 16;" :: "r"(s), "l"(g));
}
#define CP_COMMIT() asm volatile("cp.async.commit_group;" ::: "memory")
#define CP_WAIT1()  asm volatile("cp.async.wait_group 1;"  ::: "memory")

__device__ __forceinline__ void ldsm4(uint32_t addr, uint32_t r[4]) {
    asm volatile("ldmatrix.sync.aligned.m8n8.x4.shared.b16 {%0,%1,%2,%3}, [%4];"
                 : "=r"(r[0]), "=r"(r[1]), "=r"(r[2]), "=r"(r[3]) : "r"(addr));
}

__device__ __forceinline__ void mma16816(float c[4], const uint32_t a[4],
                                         uint32_t b0, uint32_t b1) {
    asm volatile(
        "mma.sync.aligned.m16n8k16.row.col.f32.f16.f16.f32 "
        "{%0,%1,%2,%3}, {%4,%5,%6,%7}, {%8,%9}, {%0,%1,%2,%3};"
        : "+f"(c[0]), "+f"(c[1]), "+f"(c[2]), "+f"(c[3])
        : "r"(a[0]), "r"(a[1]), "r"(a[2]), "r"(a[3]), "r"(b0), "r"(b1));
}

// ---------------- shared memory layout (per CTA) ----------------
// [0,256)        stm   (64 f32 — pair rows of this CTA)
// [256,1280)     ft_b  (256 f32)
// [1536,17920)   l1_w  [2 sides][8][256] f32 = 16 KB
// [17920, ...)   3 pipeline stages, 48 KB each: A 16 KB (128 rows) | B 32 KB (256 rows)
// stage 0's A area is reused post-mainloop as the cross-Np reduction buffer (8 KB).
#define SO_FTB   256
#define SO_L1W   1536
#define SO_TILES 17920
#define STAGE_B  49152
#define SMEM_TOTAL (SO_TILES + 3 * STAGE_B)   // 165376 (161.5 KB) -> 1 CTA/SM

// Tile layout: [rows][64 fp16] = 128 B/row; byte off = row*128 + (colb ^ ((row&7)<<4))

// ---------------- kernel 1: fp32 -> fp16 prepass ----------------
__global__ void nnue_prepass_kernel(const float* __restrict__ wht,
                                    const float* __restrict__ blk,
                                    const float* __restrict__ ftw, int Bsz) {
    size_t nA = (size_t)Bsz * (KDIM / 4);
    size_t nW = (size_t)HDIM * (KDIM / 4);
    size_t total = 2 * nA + nW;
    for (size_t i = (size_t)blockIdx.x * blockDim.x + threadIdx.x; i < total;
         i += (size_t)gridDim.x * blockDim.x) {
        const float4* src; __half* dst; size_t j;
        if (i < nA)          { src = (const float4*)wht; j = i;          dst = g_Ah; }
        else if (i < 2 * nA) { src = (const float4*)blk; j = i - nA;     dst = g_Ah + (size_t)Bsz * KDIM; }
        else                 { src = (const float4*)ftw; j = i - 2 * nA; dst = g_Bh; }
        float4 v = src[j];
        __half2 p0 = __floats2half2_rn(v.x, v.y);
        __half2 p1 = __floats2half2_rn(v.z, v.w);
        uint2 u;
        u.x = *(const unsigned int*)&p0;
        u.y = *(const unsigned int*)&p1;
        *(uint2*)(dst + 4 * j) = u;
    }
}

// ---------------- kernel 2: fused ft-GEMM + blend/clip + l1 partials ----------------
__global__ void __launch_bounds__(GT, 1)
nnue_gemm_kernel(const float* __restrict__ stm, const float* __restrict__ ft_b,
                 const float* __restrict__ l1_w, int Bsz) {
    extern __shared__ char smem[];
    uint32_t sb = smem_u32(smem);
    int tid = threadIdx.x;
    int wid = tid >> 5, L = tid & 31;
    int nt = blockIdx.x;               // 0..3  (N tile of 256 within H)
    int rb = blockIdx.y;               // 0..Bsz/64-1 (64 white+black pair rows)
    int n0 = nt * 256;

    // ---- load per-CTA params into smem ----
    if (tid < 64) ((float*)smem)[tid] = stm[rb * 64 + tid];
    *(float*)(smem + SO_FTB + tid * 4) = ft_b[n0 + tid];
    #pragma unroll
    for (int i = tid; i < 4096; i += GT) {
        int side = i >> 11, j = (i >> 8) & 7, cc = i & 255;
        ((float*)(smem + SO_L1W))[i] = l1_w[j * (2 * HDIM) + side * HDIM + n0 + cc];
    }

    const __half* Aw = g_Ah + (size_t)rb * 64 * KDIM;
    const __half* Ab = g_Ah + ((size_t)Bsz + (size_t)rb * 64) * KDIM;
    const __half* Bw = g_Bh + (size_t)n0 * KDIM;
    uint32_t tiles = sb + SO_TILES;

    // stage fill: 3072 x 16B chunks (A 1024: rows 0..127 = 64w+64b, B 2048: rows 0..255)
    auto load_stage = [&](int c) {
        int kc = c * 64;
        uint32_t base = tiles + (uint32_t)(c % 3) * STAGE_B;
        #pragma unroll
        for (int i = 0; i < 12; i++) {
            int q = tid + i * GT;
            int kb = q & 7;
            if (q < 1024) {
                int row = q >> 3;          // 0..127
                uint32_t off = (uint32_t)(row * 128 + ((kb * 16) ^ ((row & 7) << 4)));
                const __half* src = (row < 64) ? Aw + (size_t)row * KDIM
                                               : Ab + (size_t)(row - 64) * KDIM;
                cpa16(base + off, src + kc + kb * 8);
            } else {
                int row = (q - 1024) >> 3; // 0..255
                uint32_t off = (uint32_t)(16384 + row * 128 + ((kb * 16) ^ ((row & 7) << 4)));
                cpa16(base + off, Bw + (size_t)row * KDIM + kc + kb * 8);
            }
        }
    };

    // ---- per-lane ldmatrix address precompute ----
    int Mp = wid >> 2, Np = wid & 3;
    int m0w = Mp * 32, n0w = Np * 64;       // pair-rows / cols covered by this warp
    int i8 = L & 7;
    uint32_t xm  = (uint32_t)(i8 << 4);
    uint32_t khA = (uint32_t)((L >> 4) * 16);
    uint32_t khB = (uint32_t)(((L >> 3) & 1) * 16);
    uint32_t rowW[2], rowB[4];
    #pragma unroll
    for (int mt = 0; mt < 2; mt++)
        rowW[mt] = (uint32_t)((m0w + mt * 16 + i8 + ((L >> 3) & 1) * 8) * 128);  // white; black +8192
    #pragma unroll
    for (int nb = 0; nb < 4; nb++)
        rowB[nb] = (uint32_t)(16384 + (n0w + nb * 16 + i8 + ((L >> 4) & 1) * 8) * 128);

    float accW[2][8][4] = {}, accB[2][8][4] = {};   // [mt][nn][reg]

    load_stage(0); CP_COMMIT();
    load_stage(1); CP_COMMIT();

    #pragma unroll 1
    for (int c = 0; c < NCHUNK; c++) {
        CP_WAIT1();
        __syncthreads();                 // chunk c ready; stage (c-1)%3 fully consumed
        if (c + 2 < NCHUNK) load_stage(c + 2);   // writes stage (c+2)%3 == (c-1)%3
        CP_COMMIT();
        uint32_t sA = tiles + (uint32_t)(c % 3) * STAGE_B;
        #pragma unroll
        for (int st = 0; st < 4; st++) {
            uint32_t kk = (uint32_t)(st * 32);
            uint32_t aW[2][4], aK[2][4], bb[4][4];
            uint32_t adA = (kk + khA) ^ xm;
            uint32_t adB = (kk + khB) ^ xm;
            ldsm4(sA + rowW[0] + adA,        aW[0]);
            ldsm4(sA + rowW[1] + adA,        aW[1]);
            ldsm4(sA + rowW[0] + 8192 + adA, aK[0]);   // black rows at +64
            ldsm4(sA + rowW[1] + 8192 + adA, aK[1]);
            #pragma unroll
            for (int nb = 0; nb < 4; nb++) ldsm4(sA + rowB[nb] + adB, bb[nb]);
            #pragma unroll
            for (int mt = 0; mt < 2; mt++)
                #pragma unroll
                for (int nb = 0; nb < 4; nb++)
                    #pragma unroll
                    for (int h = 0; h < 2; h++) {
                        int nn = nb * 2 + h;
                        mma16816(accW[mt][nn], aW[mt], bb[nb][2 * h], bb[nb][2 * h + 1]);
                        mma16816(accB[mt][nn], aK[mt], bb[nb][2 * h], bb[nb][2 * h + 1]);
                    }
        }
    }

    // ---- epilogue: +ft_b, stm blend, clip, fused l1 partials ----
    int g = L >> 2, tg = L & 3;
    const float* stm_s = (const float*)smem;
    const float* ftb_s = (const float*)(smem + SO_FTB);
    const float* l1w0  = (const float*)(smem + SO_L1W);        // [8][256]
    const float* l1w1  = l1w0 + 2048;
    float l1acc[4][8] = {};

    #pragma unroll
    for (int mt = 0; mt < 2; mt++)
        #pragma unroll
        for (int nn = 0; nn < 8; nn++)
            #pragma unroll
            for (int cr = 0; cr < 4; cr++) {
                int pr = m0w + mt * 16 + g + (cr >> 1) * 8;      // pair row 0..63
                int cc = n0w + nn * 8 + 2 * tg + (cr & 1);       // col 0..255
                float fb = ftb_s[cc];
                float wv = accW[mt][nn][cr] + fb;
                float bv = accB[mt][nn][cr] + fb;
                float s  = stm_s[pr];
                float a0 = __saturatef(fmaf(s, wv - bv, bv));    // cols [0,H)
                float a1 = __saturatef(fmaf(s, bv - wv, wv));    // cols [H,2H)
                int rs = mt * 2 + (cr >> 1);
                #pragma unroll
                for (int j = 0; j < 8; j++)
                    l1acc[rs][j] += a0 * l1w0[j * 256 + cc] + a1 * l1w1[j * 256 + cc];
            }

    // quad reduce (lanes sharing g): sum over tg (8 col-pairs each)
    #pragma unroll
    for (int rs = 0; rs < 4; rs++)
        #pragma unroll
        for (int j = 0; j < 8; j++) {
            float v = l1acc[rs][j];
            v += __shfl_xor_sync(0xffffffffu, v, 1);
            v += __shfl_xor_sync(0xffffffffu, v, 2);
            l1acc[rs][j] = v;
        }

    // ---- cross-Np reduction in smem (alias stage-0 A area, idle now) ----
    float* red = (float*)(smem + SO_TILES);     // [4 Np][64 rows][8]
    __syncthreads();                            // all mainloop smem reads done
    if (tg == 0) {
        #pragma unroll
        for (int rs = 0; rs < 4; rs++) {
            int row = m0w + (rs >> 1) * 16 + g + (rs & 1) * 8;   // 0..63
            float* dst = red + ((size_t)Np * 64 + row) * 8;
            *(float4*)dst       = make_float4(l1acc[rs][0], l1acc[rs][1], l1acc[rs][2], l1acc[rs][3]);
            *(float4*)(dst + 4) = make_float4(l1acc[rs][4], l1acc[rs][5], l1acc[rs][6], l1acc[rs][7]);
        }
    }
    __syncthreads();
    for (int idx = tid; idx < 512; idx += GT) {
        int row = idx >> 3, j = idx & 7;
        float s = red[(0 * 64 + row) * 8 + j] + red[(1 * 64 + row) * 8 + j]
                + red[(2 * 64 + row) * 8 + j] + red[(3 * 64 + row) * 8 + j];
        g_l1part[((size_t)nt * Bsz + rb * 64 + row) * 8 + j] = s;
    }
}

// ---------------- kernel 3: reduce partials + l1_b + l2 + l3 + sigmoid ----------------
__global__ void nnue_final_kernel(const float* __restrict__ l1b, const float* __restrict__ l2w,
                                  const float* __restrict__ l2b, const float* __restrict__ l3w,
                                  const float* __restrict__ l3b, float* __restrict__ out, int Bsz) {
    int i = blockIdx.x * blockDim.x + threadIdx.x;
    if (i >= Bsz) return;
    float a[8];
    #pragma unroll
    for (int j = 0; j < 8; j++) a[j] = __ldg(l1b + j);
    #pragma unroll
    for (int sl = 0; sl < 4; sl++) {
        const float4* p = (const float4*)(g_l1part + ((size_t)sl * Bsz + i) * 8);
        float4 u = p[0], v = p[1];
        a[0] += u.x; a[1] += u.y; a[2] += u.z; a[3] += u.w;
        a[4] += v.x; a[5] += v.y; a[6] += v.z; a[7] += v.w;
    }
    #pragma unroll
    for (int j = 0; j < 8; j++) a[j] = __saturatef(a[j]);
    float raw = __ldg(l3b);
    #pragma unroll
    for (int k = 0; k < 32; k++) {
        float t = __ldg(l2b + k);
        #pragma unroll
        for (int j = 0; j < 8; j++) t = fmaf(a[j], __ldg(l2w + k * 8 + j), t);
        raw = fmaf(__saturatef(t), __ldg(l3w + k), raw);
    }
    out[i]       = 1.f / (1.f + __expf(-raw));
    out[Bsz + i] = raw;
}

// ---------------- launch ----------------
extern "C" void kernel_launch(void* const* d_in, const int* in_sizes, int n_in,
                              void* d_out, int out_size) {
    const float* wht = (const float*)d_in[0];
    const float* blk = (const float*)d_in[1];
    const float* stm = (const float*)d_in[2];
    const float* ftw = (const float*)d_in[3];
    const float* ftb = (const float*)d_in[4];
    const float* l1w = (const float*)d_in[5];
    const float* l1b = (const float*)d_in[6];
    const float* l2w = (const float*)d_in[7];
    const float* l2b = (const float*)d_in[8];
    const float* l3w = (const float*)d_in[9];
    const float* l3b = (const float*)d_in[10];
    float* out = (float*)d_out;
    int Bsz = in_sizes[0] / KDIM;

    nnue_prepass_kernel<<<4096, 256>>>(wht, blk, ftw, Bsz);

    static int smem_set = 0;
    if (!smem_set) {
        cudaFuncSetAttribute(nnue_gemm_kernel,
                             cudaFuncAttributeMaxDynamicSharedMemorySize, SMEM_TOTAL);
        smem_set = 1;
    }
    dim3 grid(HDIM / 256, Bsz / 64);   // (4, 1024); x-fastest: N-tiles of a row-block share A in L2
    nnue_gemm_kernel<<<grid, GT, SMEM_TOTAL>>>(stm, ftb, l1w, Bsz);

    nnue_final_kernel<<<(Bsz + 255) / 256, 256>>>(l1b, l2w, l2b, l3w, l3b, out, Bsz);
}

// round 15
// speedup vs baseline: 1.3572x; 1.3572x over previous
#include <cuda_runtime.h>
#include <cuda_fp16.h>
#include <cstdint>

// ---------------- problem constants ----------------
#define KDIM   768
#define HDIM   1024
#define BMAX   65536
#define GT     256          // 8 warps: 2 Mp x 4 Np
#define NCHUNK (KDIM / 64)  // 12 K-chunks of 64

// ---------------- scratch (device globals; no allocation APIs) ----------------
__device__ __align__(256) __half g_Ah[(size_t)2 * BMAX * KDIM];  // [white;black] fp16
__device__ __align__(256) __half g_Bh[(size_t)HDIM * KDIM];      // ft_w fp16
__device__ __align__(256) float  g_l1part[(size_t)8 * BMAX * 8]; // [slot][row][8]

// ---------------- PTX helpers (plain sm_103-safe: cp.async / ldmatrix / mma.sync) ----
__device__ __forceinline__ uint32_t smem_u32(const void* p) {
    uint32_t a;
    asm("{ .reg .u64 t; cvta.to.shared.u64 t, %1; cvt.u32.u64 %0, t; }" : "=r"(a) : "l"(p));
    return a;
}

__device__ __forceinline__ void cpa16(uint32_t s, const void* g) {
    asm volatile("cp.async.cg.shared.global [%0], [%1], 16;" :: "r"(s), "l"(g));
}
#define CP_COMMIT() asm volatile("cp.async.commit_group;" ::: "memory")
#define CP_WAIT1()  asm volatile("cp.async.wait_group 1;"  ::: "memory")

__device__ __forceinline__ void ldsm4(uint32_t addr, uint32_t r[4]) {
    asm volatile("ldmatrix.sync.aligned.m8n8.x4.shared.b16 {%0,%1,%2,%3}, [%4];"
                 : "=r"(r[0]), "=r"(r[1]), "=r"(r[2]), "=r"(r[3]) : "r"(addr));
}

__device__ __forceinline__ void mma16816(float c[4], const uint32_t a[4],
                                         uint32_t b0, uint32_t b1) {
    asm volatile(
        "mma.sync.aligned.m16n8k16.row.col.f32.f16.f16.f32 "
        "{%0,%1,%2,%3}, {%4,%5,%6,%7}, {%8,%9}, {%0,%1,%2,%3};"
        : "+f"(c[0]), "+f"(c[1]), "+f"(c[2]), "+f"(c[3])
        : "r"(a[0]), "r"(a[1]), "r"(a[2]), "r"(a[3]), "r"(b0), "r"(b1));
}

// ---------------- shared memory layout (per CTA) ----------------
// [0,256)      stm   (64 f32 — pair rows of this CTA)
// [256,768)    ft_b  (128 f32)
// [1024,9216)  l1_w  [2 sides][8][128] f32
// [9216, ...)  3 pipeline stages, 32 KB each: A 16 KB (128 rows) | B 16 KB (128 rows)
// stage 0's A area is reused post-mainloop as the cross-Np reduction buffer (8 KB).
#define SO_FTB   256
#define SO_L1W   1024
#define SO_TILES 9216
#define STAGE_B  32768
#define SMEM_TOTAL (SO_TILES + 3 * STAGE_B)   // 107520 -> 2 CTAs/SM (215 KB)

// Tile layout: [rows][64 fp16] = 128 B/row; byte off = row*128 + (colb ^ ((row&7)<<4))

// ---------------- kernel 1: fp32 -> fp16 prepass ----------------
__global__ void nnue_prepass_kernel(const float* __restrict__ wht,
                                    const float* __restrict__ blk,
                                    const float* __restrict__ ftw, int Bsz) {
    size_t nA = (size_t)Bsz * (KDIM / 4);
    size_t nW = (size_t)HDIM * (KDIM / 4);
    size_t total = 2 * nA + nW;
    for (size_t i = (size_t)blockIdx.x * blockDim.x + threadIdx.x; i < total;
         i += (size_t)gridDim.x * blockDim.x) {
        const float4* src; __half* dst; size_t j;
        if (i < nA)          { src = (const float4*)wht; j = i;          dst = g_Ah; }
        else if (i < 2 * nA) { src = (const float4*)blk; j = i - nA;     dst = g_Ah + (size_t)Bsz * KDIM; }
        else                 { src = (const float4*)ftw; j = i - 2 * nA; dst = g_Bh; }
        float4 v = src[j];
        __half2 p0 = __floats2half2_rn(v.x, v.y);
        __half2 p1 = __floats2half2_rn(v.z, v.w);
        uint2 u;
        u.x = *(const unsigned int*)&p0;
        u.y = *(const unsigned int*)&p1;
        *(uint2*)(dst + 4 * j) = u;
    }
}

// ---------------- kernel 2: fused ft-GEMM + blend/clip + l1 partials (mma epilogue) ----
__global__ void __launch_bounds__(GT, 2)
nnue_gemm_kernel(const float* __restrict__ stm, const float* __restrict__ ft_b,
                 const float* __restrict__ l1_w, int Bsz) {
    extern __shared__ char smem[];
    uint32_t sb = smem_u32(smem);
    int tid = threadIdx.x;
    int wid = tid >> 5, L = tid & 31;
    int nt = blockIdx.x;               // 0..7  (N tile of 128 within H)
    int rb = blockIdx.y;               // 0..Bsz/64-1 (64 white+black pair rows)
    int n0 = nt * 128;

    // ---- load per-CTA params into smem ----
    if (tid < 64)  ((float*)smem)[tid] = stm[rb * 64 + tid];
    if (tid < 128) *(float*)(smem + SO_FTB + tid * 4) = ft_b[n0 + tid];
    #pragma unroll
    for (int i = tid; i < 2048; i += GT) {
        int side = i >> 10, j = (i >> 7) & 7, cc = i & 127;
        ((float*)(smem + SO_L1W))[i] = l1_w[j * (2 * HDIM) + side * HDIM + n0 + cc];
    }

    const __half* Aw = g_Ah + (size_t)rb * 64 * KDIM;
    const __half* Ab = g_Ah + ((size_t)Bsz + (size_t)rb * 64) * KDIM;
    const __half* Bw = g_Bh + (size_t)n0 * KDIM;
    uint32_t tiles = sb + SO_TILES;

    // stage fill: 2048 x 16B chunks (A 1024: rows 0..127 = 64w+64b, B 1024), 8/thread
    auto load_stage = [&](int c) {
        int kc = c * 64;
        uint32_t base = tiles + (uint32_t)(c % 3) * STAGE_B;
        #pragma unroll
        for (int i = 0; i < 8; i++) {
            int q = tid + i * GT;
            int row = (q >> 3) & 127, kb = q & 7;
            uint32_t off = (uint32_t)(row * 128 + ((kb * 16) ^ ((row & 7) << 4)));
            if (q < 1024) {
                const __half* src = (row < 64) ? Aw + (size_t)row * KDIM
                                               : Ab + (size_t)(row - 64) * KDIM;
                cpa16(base + off, src + kc + kb * 8);
            } else {
                cpa16(base + 16384 + off, Bw + (size_t)row * KDIM + kc + kb * 8);
            }
        }
    };

    // ---- per-lane ldmatrix address precompute ----
    int Mp = wid >> 2, Np = wid & 3;
    int m0w = Mp * 32, n0w = Np * 32;       // pair-rows / cols covered by this warp
    int i8 = L & 7;
    uint32_t xm  = (uint32_t)(i8 << 4);
    uint32_t khA = (uint32_t)((L >> 4) * 16);
    uint32_t khB = (uint32_t)(((L >> 3) & 1) * 16);
    uint32_t rowW[2], rowB[2];
    #pragma unroll
    for (int mt = 0; mt < 2; mt++)
        rowW[mt] = (uint32_t)((m0w + mt * 16 + i8 + ((L >> 3) & 1) * 8) * 128);  // white; black at +8192
    #pragma unroll
    for (int nb = 0; nb < 2; nb++)
        rowB[nb] = (uint32_t)(16384 + (n0w + nb * 16 + i8 + ((L >> 4) & 1) * 8) * 128);

    float accW[2][4][4] = {}, accB[2][4][4] = {};   // [mt][nn][reg]

    load_stage(0); CP_COMMIT();
    load_stage(1); CP_COMMIT();

    #pragma unroll 1
    for (int c = 0; c < NCHUNK; c++) {
        CP_WAIT1();
        __syncthreads();                 // chunk c ready; stage (c-1)%3 fully consumed
        if (c + 2 < NCHUNK) load_stage(c + 2);   // writes stage (c+2)%3 == (c-1)%3
        CP_COMMIT();
        uint32_t sA = tiles + (uint32_t)(c % 3) * STAGE_B;
        #pragma unroll
        for (int st = 0; st < 4; st++) {
            uint32_t kk = (uint32_t)(st * 32);
            uint32_t aW[2][4], aK[2][4], bb[2][4];
            uint32_t adA = (kk + khA) ^ xm;
            uint32_t adB = (kk + khB) ^ xm;
            ldsm4(sA + rowW[0] + adA,        aW[0]);
            ldsm4(sA + rowW[1] + adA,        aW[1]);
            ldsm4(sA + rowW[0] + 8192 + adA, aK[0]);   // black rows at +64
            ldsm4(sA + rowW[1] + 8192 + adA, aK[1]);
            ldsm4(sA + rowB[0] + adB,        bb[0]);
            ldsm4(sA + rowB[1] + adB,        bb[1]);
            #pragma unroll
            for (int mt = 0; mt < 2; mt++)
                #pragma unroll
                for (int nb = 0; nb < 2; nb++)
                    #pragma unroll
                    for (int h = 0; h < 2; h++) {
                        int nn = nb * 2 + h;
                        mma16816(accW[mt][nn], aW[mt], bb[nb][2 * h], bb[nb][2 * h + 1]);
                        mma16816(accB[mt][nn], aK[mt], bb[nb][2 * h], bb[nb][2 * h + 1]);
                    }
        }
    }

    // ---- epilogue: +ft_b, stm blend, clip, then l1 layer as tiny mma (N=8 outputs) ----
    // Activation C-fragments re-pack EXACTLY into m16k16 A-fragments:
    //   a0=(row g, k 2tg..+1)  a1=(row g+8, same k)  a2=(row g, k+8)  a3=(row g+8, k+8)
    // B-fragment (l1_w, k x n col-major): lane l: b0 = w[n=g][k=2tg..+1], b1 = +8.
    int g = L >> 2, tg = L & 3;
    const float* stm_s = (const float*)smem;
    const float* ftb_s = (const float*)(smem + SO_FTB);
    const float* l1w0  = (const float*)(smem + SO_L1W);        // [8][128]
    const float* l1w1  = l1w0 + 1024;

    // constant l1_w B-fragments: [kb 2][side 2][2 regs]
    uint32_t bfr[2][2][2];
    #pragma unroll
    for (int kb = 0; kb < 2; kb++)
        #pragma unroll
        for (int sd = 0; sd < 2; sd++) {
            const float* w = sd ? l1w1 : l1w0;
            int cb = n0w + kb * 16 + 2 * tg;
            __half2 b0 = __floats2half2_rn(w[g * 128 + cb],     w[g * 128 + cb + 1]);
            __half2 b1 = __floats2half2_rn(w[g * 128 + cb + 8], w[g * 128 + cb + 9]);
            bfr[kb][sd][0] = *(uint32_t*)&b0;
            bfr[kb][sd][1] = *(uint32_t*)&b1;
        }

    float cL1[2][4] = {};   // [mt][C-frag]: rows {g,g+8}+mt*16+m0w, l1 outputs {2tg,2tg+1}
    #pragma unroll
    for (int mt = 0; mt < 2; mt++) {
        uint32_t pa0[4][2], pa1[4][2];   // [nn][rowhalf] packed half2 (k-pair)
        #pragma unroll
        for (int nn = 0; nn < 4; nn++) {
            float a0v[4], a1v[4];
            #pragma unroll
            for (int cr = 0; cr < 4; cr++) {
                int pr = m0w + mt * 16 + g + (cr >> 1) * 8;      // pair row 0..63
                int cc = n0w + nn * 8 + 2 * tg + (cr & 1);
                float fb = ftb_s[cc];
                float wv = accW[mt][nn][cr] + fb;
                float bv = accB[mt][nn][cr] + fb;
                float s  = stm_s[pr];
                a0v[cr] = __saturatef(fmaf(s, wv - bv, bv));     // cols [0,H)
                a1v[cr] = __saturatef(fmaf(s, bv - wv, wv));     // cols [H,2H)
            }
            __half2 h;
            h = __floats2half2_rn(a0v[0], a0v[1]); pa0[nn][0] = *(uint32_t*)&h;
            h = __floats2half2_rn(a0v[2], a0v[3]); pa0[nn][1] = *(uint32_t*)&h;
            h = __floats2half2_rn(a1v[0], a1v[1]); pa1[nn][0] = *(uint32_t*)&h;
            h = __floats2half2_rn(a1v[2], a1v[3]); pa1[nn][1] = *(uint32_t*)&h;
        }
        #pragma unroll
        for (int kb = 0; kb < 2; kb++) {
            uint32_t af[4];
            af[0] = pa0[2 * kb][0]; af[1] = pa0[2 * kb][1];
            af[2] = pa0[2 * kb + 1][0]; af[3] = pa0[2 * kb + 1][1];
            mma16816(cL1[mt], af, bfr[kb][0][0], bfr[kb][0][1]);
            af[0] = pa1[2 * kb][0]; af[1] = pa1[2 * kb][1];
            af[2] = pa1[2 * kb + 1][0]; af[3] = pa1[2 * kb + 1][1];
            mma16816(cL1[mt], af, bfr[kb][1][0], bfr[kb][1][1]);
        }
    }

    // ---- cross-Np reduction in smem (alias stage-0 A area, idle now) ----
    float* red = (float*)(smem + SO_TILES);     // [4 Np][64 rows][8]
    __syncthreads();                            // all mainloop smem reads done
    #pragma unroll
    for (int mt = 0; mt < 2; mt++)
        #pragma unroll
        for (int ci = 0; ci < 4; ci++) {
            int row = m0w + mt * 16 + g + (ci >> 1) * 8;         // 0..63
            red[((size_t)Np * 64 + row) * 8 + 2 * tg + (ci & 1)] = cL1[mt][ci];
        }
    __syncthreads();
    for (int idx = tid; idx < 512; idx += GT) {
        int row = idx >> 3, j = idx & 7;
        float s = red[(0 * 64 + row) * 8 + j] + red[(1 * 64 + row) * 8 + j]
                + red[(2 * 64 + row) * 8 + j] + red[(3 * 64 + row) * 8 + j];
        g_l1part[((size_t)nt * Bsz + rb * 64 + row) * 8 + j] = s;
    }
}

// ---------------- kernel 3: reduce partials + l1_b + l2 + l3 + sigmoid ----------------
__global__ void nnue_final_kernel(const float* __restrict__ l1b, const float* __restrict__ l2w,
                                  const float* __restrict__ l2b, const float* __restrict__ l3w,
                                  const float* __restrict__ l3b, float* __restrict__ out, int Bsz) {
    int i = blockIdx.x * blockDim.x + threadIdx.x;
    if (i >= Bsz) return;
    float a[8];
    #pragma unroll
    for (int j = 0; j < 8; j++) a[j] = __ldg(l1b + j);
    #pragma unroll
    for (int sl = 0; sl < 8; sl++) {
        const float4* p = (const float4*)(g_l1part + ((size_t)sl * Bsz + i) * 8);
        float4 u = p[0], v = p[1];
        a[0] += u.x; a[1] += u.y; a[2] += u.z; a[3] += u.w;
        a[4] += v.x; a[5] += v.y; a[6] += v.z; a[7] += v.w;
    }
    #pragma unroll
    for (int j = 0; j < 8; j++) a[j] = __saturatef(a[j]);
    float raw = __ldg(l3b);
    #pragma unroll
    for (int k = 0; k < 32; k++) {
        float t = __ldg(l2b + k);
        #pragma unroll
        for (int j = 0; j < 8; j++) t = fmaf(a[j], __ldg(l2w + k * 8 + j), t);
        raw = fmaf(__saturatef(t), __ldg(l3w + k), raw);
    }
    out[i]       = 1.f / (1.f + __expf(-raw));
    out[Bsz + i] = raw;
}

// ---------------- launch ----------------
extern "C" void kernel_launch(void* const* d_in, const int* in_sizes, int n_in,
                              void* d_out, int out_size) {
    const float* wht = (const float*)d_in[0];
    const float* blk = (const float*)d_in[1];
    const float* stm = (const float*)d_in[2];
    const float* ftw = (const float*)d_in[3];
    const float* ftb = (const float*)d_in[4];
    const float* l1w = (const float*)d_in[5];
    const float* l1b = (const float*)d_in[6];
    const float* l2w = (const float*)d_in[7];
    const float* l2b = (const float*)d_in[8];
    const float* l3w = (const float*)d_in[9];
    const float* l3b = (const float*)d_in[10];
    float* out = (float*)d_out;
    int Bsz = in_sizes[0] / KDIM;

    nnue_prepass_kernel<<<4096, 256>>>(wht, blk, ftw, Bsz);

    static int smem_set = 0;
    if (!smem_set) {
        cudaFuncSetAttribute(nnue_gemm_kernel,
                             cudaFuncAttributeMaxDynamicSharedMemorySize, SMEM_TOTAL);
        smem_set = 1;
    }
    dim3 grid(HDIM / 128, Bsz / 64);   // (8, 1024); x-fastest: N-tiles of a row-block share A in L2
    nnue_gemm_kernel<<<grid, GT, SMEM_TOTAL>>>(stm, ftb, l1w, Bsz);

    nnue_final_kernel<<<(Bsz + 255) / 256, 256>>>(l1b, l2w, l2b, l3w, l3b, out, Bsz);
}